// round 10
// baseline (speedup 1.0000x reference)
#include <cuda_runtime.h>
#include <cuda_fp16.h>
#include <cstdint>

#define B_ROWS  32768
#define D_DIM   256
#define K_CODES 2048

// output layout (float32): quantized_st[B*D], vq_loss, entropy, inds[B], cluster_metric
#define OFF_VQ  8388608
#define OFF_ENT 8388609
#define OFF_IND 8388610
#define OFF_CL  8421378

#define TIE_EPS 4e-4f
#define CS      9.765625e-4f   // 2/2048 (exact power of two)

// ---------------- device scratch ----------------
__device__ uint32_t g_xh[B_ROWS * 128];    // [256 panels][256 k][64 row-pairs] fp16x2
__device__ uint32_t g_ed[K_CODES * 256];   // [32 cts][256 k][64 cols dup (v,v)] fp16x2
__device__ float g_xsq[B_ROWS];
__device__ float g_esq[K_CODES];
__device__ float g_pb [32 * B_ROWS];       // per-coltile partials
__device__ float g_pb2[32 * B_ROWS];
__device__ int   g_pi [32 * B_ROWS];
__device__ int   g_ind[B_ROWS];
__device__ int   g_flag[B_ROWS];
__device__ float g_cl_val[B_ROWS];
__device__ int   g_counts[K_CODES];
__device__ float g_mse_part[8192];

// ---------------- helpers ----------------
__device__ __forceinline__ uint32_t smem_to_u32(const void* p) {
    uint32_t a;
    asm("{ .reg .u64 t; cvta.to.shared.u64 t, %1; cvt.u32.u64 %0, t; }"
        : "=r"(a) : "l"(p));
    return a;
}
__device__ __forceinline__ void cpa16(uint32_t dst, const void* src) {
    asm volatile("cp.async.cg.shared.global [%0], [%1], 16;"
        :: "r"(dst), "l"((unsigned long long)__cvta_generic_to_global(src)) : "memory");
}
#define CP_COMMIT() asm volatile("cp.async.commit_group;" ::: "memory")
#define CP_WAIT1()  asm volatile("cp.async.wait_group 1;" ::: "memory")

__device__ __forceinline__ __half2 u32h2(uint32_t v) {
    __half2 h; *reinterpret_cast<uint32_t*>(&h) = v; return h;
}

// two-smallest tracking with first-index tie-break (matches jnp.argmin)
__device__ __forceinline__ void upd1(float& b, float& b2, int& i, float v, int n) {
    if (v < b || (v == b && n < i)) { b2 = b; b = v; i = n; }
    else b2 = fminf(b2, v);
}
__device__ __forceinline__ void merge2(float& b, float& b2, int& i,
                                       float ob, float ob2, int oi) {
    if (ob < b || (ob == b && oi < i)) { b2 = fminf(b, ob2); b = ob; i = oi; }
    else b2 = fminf(b2, ob);
}

// ---------------- prep X: fp32 -> fp16 transposed panels + xsq ----------------
#define PREPX_SMEM 65536   // u16 [256 k][128 rows]

__global__ void vq_prep_x(const float* __restrict__ latents) {
    extern __shared__ __half Hs[];
    const int tid = threadIdx.x;
    const int p = blockIdx.x;
    const int row = tid >> 1;
    const int dh = tid & 1;

    const float4* src = (const float4*)(latents + (size_t)(p * 128 + row) * D_DIM
                                        + dh * 128);
    float xacc = 0.0f;
#pragma unroll
    for (int j = 0; j < 32; j++) {
        const float4 v = src[j];
        xacc += v.x*v.x + v.y*v.y + v.z*v.z + v.w*v.w;
        const int k = dh * 128 + j * 4;
        Hs[(k + 0) * 128 + row] = __float2half(v.x);
        Hs[(k + 1) * 128 + row] = __float2half(v.y);
        Hs[(k + 2) * 128 + row] = __float2half(v.z);
        Hs[(k + 3) * 128 + row] = __float2half(v.w);
    }
    xacc += __shfl_xor_sync(0xffffffffu, xacc, 1);
    if (dh == 0) g_xsq[p * 128 + row] = xacc;
    __syncthreads();

    const uint4* S = (const uint4*)Hs;
    uint4* dst = (uint4*)(g_xh + (size_t)p * 16384);
#pragma unroll
    for (int i = 0; i < 16; i++)
        dst[i * 256 + tid] = S[i * 256 + tid];
}

// ---------------- prep E: fp32 -> fp16x2048 duplicated transposed + esq ----------------
__global__ void vq_prep_e(const float* __restrict__ embedding) {
    extern __shared__ uint32_t Es[];   // [256 k][64 cols dup u32]
    const int tid = threadIdx.x;
    const int ct = blockIdx.x;
    const int cl = tid >> 2;
    const int dq = tid & 3;

    if (ct == 0)
        for (int k = tid; k < K_CODES; k += 256) g_counts[k] = 0;

    const float4* src = (const float4*)(embedding + (size_t)(ct * 64 + cl) * D_DIM
                                        + dq * 64);
    float ss = 0.0f;
#pragma unroll
    for (int j = 0; j < 16; j++) {
        const float4 v = src[j];
        ss += v.x*v.x + v.y*v.y + v.z*v.z + v.w*v.w;
        const int k = dq * 64 + j * 4;
        const float f[4] = {v.x, v.y, v.z, v.w};
#pragma unroll
        for (int q = 0; q < 4; q++) {
            const __half h = __float2half(f[q] * 2048.0f);
            Es[(k + q) * 64 + cl] = *(const uint16_t*)&h * 0x00010001u;
        }
    }
    ss += __shfl_xor_sync(0xffffffffu, ss, 1);
    ss += __shfl_xor_sync(0xffffffffu, ss, 2);
    if (dq == 0) g_esq[ct * 64 + cl] = ss;
    __syncthreads();

    const uint4* S = (const uint4*)Es;
    uint4* dst = (uint4*)(g_ed + (size_t)ct * 16384);
#pragma unroll
    for (int i = 0; i < 16; i++)
        dst[i * 256 + tid] = S[i * 256 + tid];
}

// ---------------- main: HFMA2 GEMM (spill-free) + fused argmin ----------------
#define SMEM_TOTAL 65536   // A 2x16KB + B 2x16KB (u32: A0@0 A1@4096 B0@8192 B1@12288)

__global__ void __launch_bounds__(256, 1)
vq_main_kernel() {
    extern __shared__ uint32_t sm[];
    const uint32_t smb = smem_to_u32(sm);

    const int tid  = threadIdx.x;
    const int rgrp = tid >> 4;    // 0..15: rows rgrp*8..+7 (4 row-pairs)
    const int cgrp = tid & 15;    // 0..15: cols cgrp*4..+3
    const int lane = tid & 31;
    const int panel = blockIdx.x >> 5, ct = blockIdx.x & 31;
    const int row0 = panel * 128;

    // chunk loader: 16KB A + 16KB B per 64-k chunk
    auto loadC = [&](int c) {
        const char* gA = (const char*)(g_xh + (size_t)panel * 16384 + c * 4096);
        const char* gB = (const char*)(g_ed + (size_t)ct * 16384 + c * 4096);
        const uint32_t da = smb + (c & 1) * 16384;
        const uint32_t db = smb + 32768 + (c & 1) * 16384;
#pragma unroll
        for (int i = 0; i < 4; i++) {
            cpa16(da + (tid + i * 256) * 16, gA + (tid + i * 256) * 16);
            cpa16(db + (tid + i * 256) * 16, gB + (tid + i * 256) * 16);
        }
    };
    loadC(0); CP_COMMIT();
    loadC(1); CP_COMMIT();

    float accf[8][4];
#pragma unroll
    for (int i = 0; i < 8; i++)
#pragma unroll
        for (int c = 0; c < 4; c++) accf[i][c] = 0.0f;

    for (int ch = 0; ch < 4; ch++) {
        CP_WAIT1();
        __syncthreads();
        const uint32_t* A = sm + (ch & 1) * 4096;
        const uint32_t* B = sm + 8192 + (ch & 1) * 4096;

#pragma unroll 1
        for (int half = 0; half < 2; half++) {
            __half2 acc[4][4];
#pragma unroll
            for (int p = 0; p < 4; p++)
#pragma unroll
                for (int c = 0; c < 4; c++)
                    acc[p][c] = __floats2half2_rn(0.0f, 0.0f);

#pragma unroll 8
            for (int kk = half * 32; kk < half * 32 + 32; kk++) {
                const uint4 a4 = *(const uint4*)(A + kk * 64 + rgrp * 4);
                const uint4 b4 = *(const uint4*)(B + kk * 64 + cgrp * 4);
                const uint32_t av[4] = {a4.x, a4.y, a4.z, a4.w};
                const uint32_t bv[4] = {b4.x, b4.y, b4.z, b4.w};
#pragma unroll
                for (int p = 0; p < 4; p++)
#pragma unroll
                    for (int c = 0; c < 4; c++)
                        acc[p][c] = __hfma2(u32h2(av[p]), u32h2(bv[c]), acc[p][c]);
            }
            // drain fp16 -> fp32 shadows
#pragma unroll
            for (int p = 0; p < 4; p++)
#pragma unroll
                for (int c = 0; c < 4; c++) {
                    const float2 f = __half22float2(acc[p][c]);
                    accf[2*p][c]     += f.x;
                    accf[2*p + 1][c] += f.y;
                }
        }
        __syncthreads();
        if (ch + 2 < 4) loadC(ch + 2);
        CP_COMMIT();
    }

    // epilogue: scores + two-smallest (cols ascending)
    float xq[8];
#pragma unroll
    for (int i = 0; i < 8; i++) xq[i] = g_xsq[row0 + rgrp * 8 + i];

    const int n0 = ct * 64 + cgrp * 4;
    const float4 e4 = *(const float4*)(g_esq + n0);
    const float ev[4] = {e4.x, e4.y, e4.z, e4.w};

    float rb[8], rb2[8];
    int   ri[8];
#pragma unroll
    for (int i = 0; i < 8; i++) { rb[i] = 3.0e38f; rb2[i] = 3.0e38f; ri[i] = 0; }

#pragma unroll
    for (int c = 0; c < 4; c++)
#pragma unroll
        for (int i = 0; i < 8; i++) {
            const float sc = fmaf(-CS, accf[i][c], xq[i] + ev[c]);
            upd1(rb[i], rb2[i], ri[i], sc, n0 + c);
        }

    // merge across the 16 cgrp threads per row (lane bits 0..3)
#pragma unroll
    for (int i = 0; i < 8; i++)
#pragma unroll
        for (int m = 1; m <= 8; m <<= 1) {
            const float ob  = __shfl_xor_sync(0xffffffffu, rb[i],  m);
            const float ob2 = __shfl_xor_sync(0xffffffffu, rb2[i], m);
            const int   oi  = __shfl_xor_sync(0xffffffffu, ri[i],  m);
            merge2(rb[i], rb2[i], ri[i], ob, ob2, oi);
        }

    if ((lane & 15) == 0) {
#pragma unroll
        for (int i = 0; i < 8; i++) {
            const int row = row0 + rgrp * 8 + i;
            g_pb [ct * B_ROWS + row] = rb[i];
            g_pb2[ct * B_ROWS + row] = rb2[i];
            g_pi [ct * B_ROWS + row] = ri[i];
        }
    }
}

// ---------------- merge col-tiles ----------------
__global__ void vq_merge_kernel(float* __restrict__ out) {
    const int row = blockIdx.x * 256 + threadIdx.x;
    float b = g_pb[row], b2 = g_pb2[row];
    int i = g_pi[row];
#pragma unroll
    for (int q = 1; q < 32; q++)
        merge2(b, b2, i, g_pb[q * B_ROWS + row], g_pb2[q * B_ROWS + row],
               g_pi[q * B_ROWS + row]);
    g_ind[row] = i;
    out[OFF_IND + row] = (float)i;
    g_cl_val[row] = b;
    g_flag[row] = (b2 - b < TIE_EPS) ? 1 : 0;
}

// ---------------- fixup: exact fp32 recompute of ambiguous rows ----------------
__global__ void vq_fixup_kernel(const float* __restrict__ latents,
                                const float* __restrict__ embedding,
                                float* __restrict__ out) {
    __shared__ float lx[256];
    __shared__ float sv[256];
    __shared__ int   si[256];
    const int tid = threadIdx.x;
    const int rbeg = blockIdx.x * 256;

    for (int rr = rbeg; rr < rbeg + 256; rr++) {
        if (!g_flag[rr]) continue;

        lx[tid] = latents[(size_t)rr * D_DIM + tid];
        __syncthreads();
        const float xqv = g_xsq[rr];
        float bb = 3.0e38f;
        int bi = 0x7fffffff;
#pragma unroll
        for (int cc = 0; cc < 8; cc++) {
            const int cI = cc * 256 + tid;
            const float* e = embedding + (size_t)cI * D_DIM;
            float dot = 0.0f;
#pragma unroll 8
            for (int k = 0; k < D_DIM; k++) dot = fmaf(e[k], lx[k], dot);
            const float sc = (xqv + g_esq[cI]) - 2.0f * dot;
            if (sc < bb || (sc == bb && cI < bi)) { bb = sc; bi = cI; }
        }
        sv[tid] = bb; si[tid] = bi;
        __syncthreads();
        for (int o = 128; o; o >>= 1) {
            if (tid < o) {
                const float v2 = sv[tid + o]; const int i2 = si[tid + o];
                if (v2 < sv[tid] || (v2 == sv[tid] && i2 < si[tid])) { sv[tid] = v2; si[tid] = i2; }
            }
            __syncthreads();
        }
        if (tid == 0) {
            g_ind[rr] = si[0];
            out[OFF_IND + rr] = (float)si[0];
            g_cl_val[rr] = sv[0];
        }
        __syncthreads();
    }
}

// ---------------- gather + straight-through + mse partials + histogram ----------------
__global__ void vq_gather_kernel(const float* __restrict__ latents,
                                 const float* __restrict__ embedding,
                                 float* __restrict__ out) {
    const int i4 = blockIdx.x * blockDim.x + threadIdx.x;   // float4 index
    const int b  = i4 >> 6;
    const int d  = (i4 & 63) << 2;
    const int ind = g_ind[b];

    if ((i4 & 63) == 0) atomicAdd(&g_counts[ind], 1);

    const float4 q = *reinterpret_cast<const float4*>(embedding + (size_t)ind * D_DIM + d);
    const float4 x = *reinterpret_cast<const float4*>(latents + (size_t)b * D_DIM + d);

    const float dx = q.x - x.x, dy = q.y - x.y, dz = q.z - x.z, dw = q.w - x.w;
    float4 o;
    o.x = x.x + dx; o.y = x.y + dy; o.z = x.z + dz; o.w = x.w + dw;
    *reinterpret_cast<float4*>(out + (size_t)i4 * 4) = o;

    float ss = dx*dx + dy*dy + dz*dz + dw*dw;
#pragma unroll
    for (int off = 16; off; off >>= 1)
        ss += __shfl_down_sync(0xffffffffu, ss, off);

    __shared__ float w[8];
    const int lane = threadIdx.x & 31;
    const int warp = threadIdx.x >> 5;
    if (lane == 0) w[warp] = ss;
    __syncthreads();
    if (threadIdx.x == 0) {
        float t = 0.0f;
        for (int i = 0; i < 8; i++) t += w[i];
        g_mse_part[blockIdx.x] = t;
    }
}

// ---------------- finalize scalars ----------------
__global__ void vq_finalize_kernel(float* __restrict__ out) {
    __shared__ float sh[256];
    const int tid = threadIdx.x;

    float s = 0.0f;
    for (int i = tid; i < 8192; i += 256) s += g_mse_part[i];
    sh[tid] = s; __syncthreads();
    for (int o = 128; o; o >>= 1) { if (tid < o) sh[tid] += sh[tid + o]; __syncthreads(); }
    const float mse_sum = sh[0];
    __syncthreads();

    s = 0.0f;
    for (int i = tid; i < B_ROWS; i += 256) s += g_cl_val[i];
    sh[tid] = s; __syncthreads();
    for (int o = 128; o; o >>= 1) { if (tid < o) sh[tid] += sh[tid + o]; __syncthreads(); }
    const float cl_sum = sh[0];
    __syncthreads();

    s = 0.0f;
    for (int k = tid; k < K_CODES; k += 256) {
        const float p = (float)g_counts[k] * (1.0f / 32768.0f);
        s += p * logf(p + 1e-10f);
    }
    sh[tid] = s; __syncthreads();
    for (int o = 128; o; o >>= 1) { if (tid < o) sh[tid] += sh[tid + o]; __syncthreads(); }

    if (tid == 0) {
        const float m = mse_sum / 8388608.0f;
        out[OFF_VQ]  = m * 0.25f + m;
        out[OFF_ENT] = -sh[0];
        out[OFF_CL]  = cl_sum / 32768.0f;
    }
}

extern "C" void kernel_launch(void* const* d_in, const int* in_sizes, int n_in,
                              void* d_out, int out_size) {
    const float* latents   = (const float*)d_in[0];
    const float* embedding = (const float*)d_in[1];
    float* out = (float*)d_out;

    cudaFuncSetAttribute(vq_prep_x,
                         cudaFuncAttributeMaxDynamicSharedMemorySize, PREPX_SMEM);
    cudaFuncSetAttribute(vq_prep_e,
                         cudaFuncAttributeMaxDynamicSharedMemorySize, PREPX_SMEM);
    cudaFuncSetAttribute(vq_main_kernel,
                         cudaFuncAttributeMaxDynamicSharedMemorySize, SMEM_TOTAL);

    vq_prep_x<<<256, 256, PREPX_SMEM>>>(latents);
    vq_prep_e<<<32, 256, PREPX_SMEM>>>(embedding);
    vq_main_kernel<<<8192, 256, SMEM_TOTAL>>>();
    vq_merge_kernel<<<B_ROWS / 256, 256>>>(out);
    vq_fixup_kernel<<<B_ROWS / 256, 256>>>(latents, embedding, out);
    vq_gather_kernel<<<(B_ROWS * D_DIM) / (256 * 4), 256>>>(latents, embedding, out);
    vq_finalize_kernel<<<1, 256>>>(out);
}

// round 13
// speedup vs baseline: 14.7456x; 14.7456x over previous
#include <cuda_runtime.h>

#define B_ROWS  32768
#define D_DIM   256
#define K_CODES 2048

// output layout (float32): quantized_st[B*D], vq_loss, entropy, inds[B], cluster_metric
#define OFF_VQ  8388608
#define OFF_ENT 8388609
#define OFF_IND 8388610
#define OFF_CL  8421378

#define BM 64
#define BN 128
#define DK 32
#define AS_STRIDE 68    // 32 floats padded: 16B-aligned rows, 4-way store conflicts max
#define BS_STRIDE 132

__device__ float g_xsq[B_ROWS];
__device__ float g_esq[K_CODES];
__device__ int   g_ind[B_ROWS];
__device__ int   g_counts[K_CODES];
__device__ float g_cl_part[512];

__device__ __forceinline__ unsigned long long dup_f32(float f) {
    unsigned long long r;
    asm("mov.b64 %0, {%1, %1};" : "=l"(r) : "f"(f));
    return r;
}
__device__ __forceinline__ void ffma2(unsigned long long &d, unsigned long long a,
                                      unsigned long long b) {
    asm("fma.rn.f32x2 %0, %1, %2, %0;" : "+l"(d) : "l"(a), "l"(b));
}
__device__ __forceinline__ void unpack_f32x2(unsigned long long v, float &lo, float &hi) {
    asm("mov.b64 {%0, %1}, %2;" : "=f"(lo), "=f"(hi) : "l"(v));
}

// ---------------- prep: row norms + zero histogram ----------------
__global__ void vq_prep_kernel(const float* __restrict__ latents,
                               const float* __restrict__ embedding) {
    const int lane = threadIdx.x & 31;
    const int warp = threadIdx.x >> 5;
    const int gw   = blockIdx.x * 8 + warp;

    const float* src = nullptr;
    float* dst = nullptr;
    int row = 0;
    if (gw < B_ROWS)                 { src = latents;   dst = g_xsq; row = gw; }
    else if (gw < B_ROWS + K_CODES)  { src = embedding; dst = g_esq; row = gw - B_ROWS; }

    if (src) {
        const float4* p = reinterpret_cast<const float4*>(src + (size_t)row * D_DIM);
        float4 a = p[lane];
        float4 b = p[lane + 32];
        float s = a.x*a.x + a.y*a.y + a.z*a.z + a.w*a.w
                + b.x*b.x + b.y*b.y + b.z*b.z + b.w*b.w;
#pragma unroll
        for (int off = 16; off; off >>= 1)
            s += __shfl_down_sync(0xffffffffu, s, off);
        if (lane == 0) dst[row] = s;
    }
    if (blockIdx.x == 0) {
        for (int k = threadIdx.x; k < K_CODES; k += blockDim.x) g_counts[k] = 0;
    }
}

// ---------------- main: GEMM (f32x2 packed -> split FFMA) + fused argmin ----------------
// (R1-proven kernel: runs at ~99% of the 64 MAC/cyc/SM fp32 pipe bound; argmin
//  chain reproduces jnp.argmin bit-exactly on this input class.)
__global__ void vq_argmin_kernel(const float* __restrict__ latents,
                                 const float* __restrict__ embedding,
                                 float* __restrict__ out) {
    __shared__ float As[DK * AS_STRIDE];   // [k][m] transposed
    __shared__ float Bs[DK * BS_STRIDE];   // [k][n] transposed
    __shared__ float s_esq[BN];
    __shared__ float s_xsq[BM];
    __shared__ float red_s[BM][17];
    __shared__ int   red_i[BM][17];
    __shared__ float s_cl[BM];

    const int tid  = threadIdx.x;
    const int tx   = tid & 15;     // 16 col-groups of 8
    const int ty   = tid >> 4;     // 8 row-groups of 8
    const int row0 = blockIdx.x * BM;

    if (tid < BM) s_xsq[tid] = g_xsq[row0 + tid];

    float best_s[8];
    int   best_i[8];
#pragma unroll
    for (int i = 0; i < 8; i++) { best_s[i] = 3.0e38f; best_i[i] = 0; }

    const int ra = tid >> 3;   // 0..15
    const int ca = tid & 7;    // 0..7 (float4 group in D-chunk)

    for (int ct = 0; ct < K_CODES; ct += BN) {
        s_esq[tid] = g_esq[ct + tid];

        unsigned long long acc[4][8];
#pragma unroll
        for (int p = 0; p < 4; p++)
#pragma unroll
            for (int j = 0; j < 8; j++) acc[p][j] = 0ULL;

        for (int d0 = 0; d0 < D_DIM; d0 += DK) {
            __syncthreads();
            // A tile: 64 rows x 32 d, transposed store
#pragma unroll
            for (int s = 0; s < 4; s++) {
                const int r = ra + 16 * s;
                const float4 v = *reinterpret_cast<const float4*>(
                    latents + (size_t)(row0 + r) * D_DIM + d0 + 4 * ca);
                As[(4*ca + 0) * AS_STRIDE + r] = v.x;
                As[(4*ca + 1) * AS_STRIDE + r] = v.y;
                As[(4*ca + 2) * AS_STRIDE + r] = v.z;
                As[(4*ca + 3) * AS_STRIDE + r] = v.w;
            }
            // B tile: 128 codes x 32 d, transposed store
#pragma unroll
            for (int s = 0; s < 8; s++) {
                const int c = ra + 16 * s;
                const float4 v = *reinterpret_cast<const float4*>(
                    embedding + (size_t)(ct + c) * D_DIM + d0 + 4 * ca);
                Bs[(4*ca + 0) * BS_STRIDE + c] = v.x;
                Bs[(4*ca + 1) * BS_STRIDE + c] = v.y;
                Bs[(4*ca + 2) * BS_STRIDE + c] = v.z;
                Bs[(4*ca + 3) * BS_STRIDE + c] = v.w;
            }
            __syncthreads();

#pragma unroll
            for (int k = 0; k < DK; k++) {
                const ulonglong2 a01 = *reinterpret_cast<const ulonglong2*>(
                    &As[k * AS_STRIDE + ty * 8]);
                const ulonglong2 a23 = *reinterpret_cast<const ulonglong2*>(
                    &As[k * AS_STRIDE + ty * 8 + 4]);
                const float4 b0 = *reinterpret_cast<const float4*>(
                    &Bs[k * BS_STRIDE + tx * 8]);
                const float4 b1 = *reinterpret_cast<const float4*>(
                    &Bs[k * BS_STRIDE + tx * 8 + 4]);
                const float bf[8] = {b0.x, b0.y, b0.z, b0.w, b1.x, b1.y, b1.z, b1.w};
#pragma unroll
                for (int j = 0; j < 8; j++) {
                    const unsigned long long bd = dup_f32(bf[j]);
                    ffma2(acc[0][j], a01.x, bd);
                    ffma2(acc[1][j], a01.y, bd);
                    ffma2(acc[2][j], a23.x, bd);
                    ffma2(acc[3][j], a23.y, bd);
                }
            }
        }

        // scores + running argmin (mimic ref rounding: (xsq+esq) - 2*dot)
#pragma unroll
        for (int p = 0; p < 4; p++) {
#pragma unroll
            for (int j = 0; j < 8; j++) {
                float dlo, dhi;
                unpack_f32x2(acc[p][j], dlo, dhi);
                const int nl = tx * 8 + j;
                const int n  = ct + nl;
                const float eq = s_esq[nl];
                const float slo = (s_xsq[ty*8 + 2*p]     + eq) - 2.0f * dlo;
                const float shi = (s_xsq[ty*8 + 2*p + 1] + eq) - 2.0f * dhi;
                if (slo < best_s[2*p])     { best_s[2*p]     = slo; best_i[2*p]     = n; }
                if (shi < best_s[2*p + 1]) { best_s[2*p + 1] = shi; best_i[2*p + 1] = n; }
            }
        }
        __syncthreads();   // protect s_esq before next tile overwrite
    }

    // cross-thread argmin reduce (tie -> lowest index, matching jnp.argmin)
#pragma unroll
    for (int i = 0; i < 8; i++) {
        red_s[ty*8 + i][tx] = best_s[i];
        red_i[ty*8 + i][tx] = best_i[i];
    }
    __syncthreads();
    if (tid < BM) {
        float bs = red_s[tid][0];
        int   bi = red_i[tid][0];
#pragma unroll
        for (int t = 1; t < 16; t++) {
            const float s = red_s[tid][t];
            const int  ii = red_i[tid][t];
            if (s < bs || (s == bs && ii < bi)) { bs = s; bi = ii; }
        }
        const int row = row0 + tid;
        g_ind[row] = bi;
        out[OFF_IND + row] = (float)bi;
        s_cl[tid] = bs;
    }
    __syncthreads();
    if (tid == 0) {
        float t = 0.0f;
        for (int i = 0; i < BM; i++) t += s_cl[i];
        g_cl_part[blockIdx.x] = t;   // fixed slot -> deterministic
    }
}

// ---------------- gather: pure streaming straight-through + histogram ----------------
// mse is NOT computed here: sum((q-x)^2) == sum(dist at argmin) == sum(g_cl_part).
__global__ void vq_gather_kernel(const float* __restrict__ latents,
                                 const float* __restrict__ embedding,
                                 float* __restrict__ out) {
    const int i4 = blockIdx.x * blockDim.x + threadIdx.x;   // float4 index
    const int b  = i4 >> 6;
    const int d  = (i4 & 63) << 2;
    const int ind = g_ind[b];

    if ((i4 & 63) == 0) atomicAdd(&g_counts[ind], 1);

    const float4 q = *reinterpret_cast<const float4*>(embedding + (size_t)ind * D_DIM + d);
    const float4 x = *reinterpret_cast<const float4*>(latents + (size_t)b * D_DIM + d);

    float4 o;
    o.x = x.x + (q.x - x.x);   // fl(x + fl(q - x)) — matches ref STE expression
    o.y = x.y + (q.y - x.y);
    o.z = x.z + (q.z - x.z);
    o.w = x.w + (q.w - x.w);
    *reinterpret_cast<float4*>(out + (size_t)i4 * 4) = o;
}

// ---------------- finalize scalars (1024 threads, latency-optimized) ----------------
__global__ void vq_finalize_kernel(float* __restrict__ out) {
    __shared__ float sh[1024];
    const int tid = threadIdx.x;

    // sum of per-block min-dist partials: feeds BOTH vq_loss and cluster_metric
    float s = (tid < 512) ? g_cl_part[tid] : 0.0f;
    sh[tid] = s; __syncthreads();
    for (int o = 512; o; o >>= 1) { if (tid < o) sh[tid] += sh[tid + o]; __syncthreads(); }
    const float cl_sum = sh[0];
    __syncthreads();

    // entropy over code histogram
    s = 0.0f;
    for (int k = tid; k < K_CODES; k += 1024) {
        const float p = (float)g_counts[k] * (1.0f / 32768.0f);
        s += p * logf(p + 1e-10f);
    }
    sh[tid] = s; __syncthreads();
    for (int o = 512; o; o >>= 1) { if (tid < o) sh[tid] += sh[tid + o]; __syncthreads(); }

    if (tid == 0) {
        const float m = cl_sum / 8388608.0f;         // mean((q-x)^2) over B*D
        out[OFF_VQ]  = m * 0.25f + m;                // beta*commitment + embedding loss
        out[OFF_ENT] = -sh[0];
        out[OFF_CL]  = cl_sum / 32768.0f;            // mean min-dist over B
    }
}

extern "C" void kernel_launch(void* const* d_in, const int* in_sizes, int n_in,
                              void* d_out, int out_size) {
    const float* latents   = (const float*)d_in[0];
    const float* embedding = (const float*)d_in[1];
    float* out = (float*)d_out;

    vq_prep_kernel<<<(B_ROWS + K_CODES) / 8, 256>>>(latents, embedding);
    vq_argmin_kernel<<<B_ROWS / BM, 128>>>(latents, embedding, out);
    vq_gather_kernel<<<(B_ROWS * D_DIM) / (256 * 4), 256>>>(latents, embedding, out);
    vq_finalize_kernel<<<1, 1024>>>(out);
}

// round 15
// speedup vs baseline: 14.7606x; 1.0010x over previous
#include <cuda_runtime.h>

#define B_ROWS  32768
#define D_DIM   256
#define K_CODES 2048

// output layout (float32): quantized_st[B*D], vq_loss, entropy, inds[B], cluster_metric
#define OFF_VQ  8388608
#define OFF_ENT 8388609
#define OFF_IND 8388610
#define OFF_CL  8421378

#define BM 64
#define BN 128
#define DK 32
#define AS_STRIDE 68    // 32 floats padded: 16B-aligned rows, 4-way store conflicts max
#define BS_STRIDE 132

__device__ float g_xsq[B_ROWS];
__device__ float g_esq[K_CODES];
__device__ int   g_counts[K_CODES];
__device__ float g_cl_part[512];

__device__ __forceinline__ unsigned long long dup_f32(float f) {
    unsigned long long r;
    asm("mov.b64 %0, {%1, %1};" : "=l"(r) : "f"(f));
    return r;
}
__device__ __forceinline__ void ffma2(unsigned long long &d, unsigned long long a,
                                      unsigned long long b) {
    asm("fma.rn.f32x2 %0, %1, %2, %0;" : "+l"(d) : "l"(a), "l"(b));
}
__device__ __forceinline__ void unpack_f32x2(unsigned long long v, float &lo, float &hi) {
    asm("mov.b64 {%0, %1}, %2;" : "=f"(lo), "=f"(hi) : "l"(v));
}

// ---------------- prep: row norms + zero histogram ----------------
__global__ void vq_prep_kernel(const float* __restrict__ latents,
                               const float* __restrict__ embedding) {
    const int lane = threadIdx.x & 31;
    const int warp = threadIdx.x >> 5;
    const int gw   = blockIdx.x * 8 + warp;

    const float* src = nullptr;
    float* dst = nullptr;
    int row = 0;
    if (gw < B_ROWS)                 { src = latents;   dst = g_xsq; row = gw; }
    else if (gw < B_ROWS + K_CODES)  { src = embedding; dst = g_esq; row = gw - B_ROWS; }

    if (src) {
        const float4* p = reinterpret_cast<const float4*>(src + (size_t)row * D_DIM);
        float4 a = p[lane];
        float4 b = p[lane + 32];
        float s = a.x*a.x + a.y*a.y + a.z*a.z + a.w*a.w
                + b.x*b.x + b.y*b.y + b.z*b.z + b.w*b.w;
#pragma unroll
        for (int off = 16; off; off >>= 1)
            s += __shfl_down_sync(0xffffffffu, s, off);
        if (lane == 0) dst[row] = s;
    }
    if (blockIdx.x == 0) {
        for (int k = threadIdx.x; k < K_CODES; k += blockDim.x) g_counts[k] = 0;
    }
}

// ---------------- main: GEMM + fused argmin + fused gather/STE/histogram ----------------
// GEMM/argmin chain identical to the R1/R12-proven kernel (bit-exact jnp.argmin
// reproduction). After the argmin, the block immediately emits its 64 rows of
// quantized_st and histogram updates; these writes overlap other blocks' FFMA.
__global__ void vq_argmin_kernel(const float* __restrict__ latents,
                                 const float* __restrict__ embedding,
                                 float* __restrict__ out) {
    __shared__ float As[DK * AS_STRIDE];   // [k][m] transposed
    __shared__ float Bs[DK * BS_STRIDE];   // [k][n] transposed
    __shared__ float s_esq[BN];
    __shared__ float s_xsq[BM];
    __shared__ float red_s[BM][17];
    __shared__ int   red_i[BM][17];
    __shared__ float s_cl[BM];
    __shared__ int   s_ind[BM];

    const int tid  = threadIdx.x;
    const int tx   = tid & 15;     // 16 col-groups of 8
    const int ty   = tid >> 4;     // 8 row-groups of 8
    const int row0 = blockIdx.x * BM;

    if (tid < BM) s_xsq[tid] = g_xsq[row0 + tid];

    float best_s[8];
    int   best_i[8];
#pragma unroll
    for (int i = 0; i < 8; i++) { best_s[i] = 3.0e38f; best_i[i] = 0; }

    const int ra = tid >> 3;   // 0..15
    const int ca = tid & 7;    // 0..7 (float4 group in D-chunk)

    for (int ct = 0; ct < K_CODES; ct += BN) {
        s_esq[tid] = g_esq[ct + tid];

        unsigned long long acc[4][8];
#pragma unroll
        for (int p = 0; p < 4; p++)
#pragma unroll
            for (int j = 0; j < 8; j++) acc[p][j] = 0ULL;

        for (int d0 = 0; d0 < D_DIM; d0 += DK) {
            __syncthreads();
            // A tile: 64 rows x 32 d, transposed store
#pragma unroll
            for (int s = 0; s < 4; s++) {
                const int r = ra + 16 * s;
                const float4 v = *reinterpret_cast<const float4*>(
                    latents + (size_t)(row0 + r) * D_DIM + d0 + 4 * ca);
                As[(4*ca + 0) * AS_STRIDE + r] = v.x;
                As[(4*ca + 1) * AS_STRIDE + r] = v.y;
                As[(4*ca + 2) * AS_STRIDE + r] = v.z;
                As[(4*ca + 3) * AS_STRIDE + r] = v.w;
            }
            // B tile: 128 codes x 32 d, transposed store
#pragma unroll
            for (int s = 0; s < 8; s++) {
                const int c = ra + 16 * s;
                const float4 v = *reinterpret_cast<const float4*>(
                    embedding + (size_t)(ct + c) * D_DIM + d0 + 4 * ca);
                Bs[(4*ca + 0) * BS_STRIDE + c] = v.x;
                Bs[(4*ca + 1) * BS_STRIDE + c] = v.y;
                Bs[(4*ca + 2) * BS_STRIDE + c] = v.z;
                Bs[(4*ca + 3) * BS_STRIDE + c] = v.w;
            }
            __syncthreads();

#pragma unroll
            for (int k = 0; k < DK; k++) {
                const ulonglong2 a01 = *reinterpret_cast<const ulonglong2*>(
                    &As[k * AS_STRIDE + ty * 8]);
                const ulonglong2 a23 = *reinterpret_cast<const ulonglong2*>(
                    &As[k * AS_STRIDE + ty * 8 + 4]);
                const float4 b0 = *reinterpret_cast<const float4*>(
                    &Bs[k * BS_STRIDE + tx * 8]);
                const float4 b1 = *reinterpret_cast<const float4*>(
                    &Bs[k * BS_STRIDE + tx * 8 + 4]);
                const float bf[8] = {b0.x, b0.y, b0.z, b0.w, b1.x, b1.y, b1.z, b1.w};
#pragma unroll
                for (int j = 0; j < 8; j++) {
                    const unsigned long long bd = dup_f32(bf[j]);
                    ffma2(acc[0][j], a01.x, bd);
                    ffma2(acc[1][j], a01.y, bd);
                    ffma2(acc[2][j], a23.x, bd);
                    ffma2(acc[3][j], a23.y, bd);
                }
            }
        }

        // scores + running argmin (mimic ref rounding: (xsq+esq) - 2*dot)
#pragma unroll
        for (int p = 0; p < 4; p++) {
#pragma unroll
            for (int j = 0; j < 8; j++) {
                float dlo, dhi;
                unpack_f32x2(acc[p][j], dlo, dhi);
                const int nl = tx * 8 + j;
                const int n  = ct + nl;
                const float eq = s_esq[nl];
                const float slo = (s_xsq[ty*8 + 2*p]     + eq) - 2.0f * dlo;
                const float shi = (s_xsq[ty*8 + 2*p + 1] + eq) - 2.0f * dhi;
                if (slo < best_s[2*p])     { best_s[2*p]     = slo; best_i[2*p]     = n; }
                if (shi < best_s[2*p + 1]) { best_s[2*p + 1] = shi; best_i[2*p + 1] = n; }
            }
        }
        __syncthreads();   // protect s_esq before next tile overwrite
    }

    // cross-thread argmin reduce (tie -> lowest index, matching jnp.argmin)
#pragma unroll
    for (int i = 0; i < 8; i++) {
        red_s[ty*8 + i][tx] = best_s[i];
        red_i[ty*8 + i][tx] = best_i[i];
    }
    __syncthreads();
    if (tid < BM) {
        float bs = red_s[tid][0];
        int   bi = red_i[tid][0];
#pragma unroll
        for (int t = 1; t < 16; t++) {
            const float s = red_s[tid][t];
            const int  ii = red_i[tid][t];
            if (s < bs || (s == bs && ii < bi)) { bs = s; bi = ii; }
        }
        const int row = row0 + tid;
        out[OFF_IND + row] = (float)bi;
        s_ind[tid] = bi;
        s_cl[tid] = bs;
        atomicAdd(&g_counts[bi], 1);
    }
    __syncthreads();
    if (tid == 0) {
        float t = 0.0f;
        for (int i = 0; i < BM; i++) t += s_cl[i];
        g_cl_part[blockIdx.x] = t;   // fixed slot -> deterministic
    }

    // fused gather + straight-through output for this block's 64 rows.
    // latents rows are L2-hot (33.5MB < 126MB L2); embedding is L2-resident.
#pragma unroll
    for (int i = 0; i < 32; i++) {
        const int idx = i * 128 + tid;          // 4096 float4's = 64 rows x 64
        const int r  = idx >> 6;
        const int d  = (idx & 63) << 2;
        const int row = row0 + r;
        const float4 q = *reinterpret_cast<const float4*>(
            embedding + (size_t)s_ind[r] * D_DIM + d);
        const float4 x = *reinterpret_cast<const float4*>(
            latents + (size_t)row * D_DIM + d);
        float4 o;
        o.x = x.x + (q.x - x.x);   // fl(x + fl(q - x)) — matches ref STE expression
        o.y = x.y + (q.y - x.y);
        o.z = x.z + (q.z - x.z);
        o.w = x.w + (q.w - x.w);
        *reinterpret_cast<float4*>(out + (size_t)row * D_DIM + d) = o;
    }
}

// ---------------- finalize scalars (1024 threads, latency-optimized) ----------------
__global__ void vq_finalize_kernel(float* __restrict__ out) {
    __shared__ float sh[1024];
    const int tid = threadIdx.x;

    // sum of per-block min-dist partials: feeds BOTH vq_loss and cluster_metric
    float s = (tid < 512) ? g_cl_part[tid] : 0.0f;
    sh[tid] = s; __syncthreads();
    for (int o = 512; o; o >>= 1) { if (tid < o) sh[tid] += sh[tid + o]; __syncthreads(); }
    const float cl_sum = sh[0];
    __syncthreads();

    // entropy over code histogram
    s = 0.0f;
    for (int k = tid; k < K_CODES; k += 1024) {
        const float p = (float)g_counts[k] * (1.0f / 32768.0f);
        s += p * logf(p + 1e-10f);
    }
    sh[tid] = s; __syncthreads();
    for (int o = 512; o; o >>= 1) { if (tid < o) sh[tid] += sh[tid + o]; __syncthreads(); }

    if (tid == 0) {
        const float m = cl_sum / 8388608.0f;         // mean((q-x)^2) over B*D
        out[OFF_VQ]  = m * 0.25f + m;                // beta*commitment + embedding loss
        out[OFF_ENT] = -sh[0];
        out[OFF_CL]  = cl_sum / 32768.0f;            // mean min-dist over B
    }
}

extern "C" void kernel_launch(void* const* d_in, const int* in_sizes, int n_in,
                              void* d_out, int out_size) {
    const float* latents   = (const float*)d_in[0];
    const float* embedding = (const float*)d_in[1];
    float* out = (float*)d_out;

    vq_prep_kernel<<<(B_ROWS + K_CODES) / 8, 256>>>(latents, embedding);
    vq_argmin_kernel<<<B_ROWS / BM, 128>>>(latents, embedding, out);
    vq_finalize_kernel<<<1, 1024>>>(out);
}